// round 2
// baseline (speedup 1.0000x reference)
#include <cuda_runtime.h>
#include <cuda_bf16.h>
#include <cstdint>

#define N_USER 100000
#define N_ITEM 50000
#define N_NODES 150000
#define N_EDGES 1200000
#define D 64
#define OUTD 256
#define NEG_SLOPE 0.01f
#define EPS_NORM 1e-12f

// Scratch (device globals allowed; no dynamic allocation)
__device__ float g_E[N_NODES * D];      // current layer embedding (unnormalized)
__device__ float g_front[N_NODES * D];  // (H+I) @ E accumulator

// ---------------------------------------------------------------------------
// helpers
// ---------------------------------------------------------------------------
__device__ __forceinline__ float lrelu(float v) {
    return v >= 0.f ? v : NEG_SLOPE * v;
}

__device__ __forceinline__ unsigned long long pk2(float lo, float hi) {
    unsigned long long r;
    asm("mov.b64 %0, {%1, %2};" : "=l"(r) : "f"(lo), "f"(hi));
    return r;
}
__device__ __forceinline__ void unpk2(float& lo, float& hi, unsigned long long v) {
    asm("mov.b64 {%0, %1}, %2;" : "=f"(lo), "=f"(hi) : "l"(v));
}
__device__ __forceinline__ void fma2(unsigned long long& d, unsigned long long a,
                                     unsigned long long b) {
    asm("fma.rn.f32x2 %0, %1, %2, %0;" : "+l"(d) : "l"(a), "l"(b));
}

__device__ __forceinline__ void red_add_v4(float* p, float a, float b, float c, float d) {
    asm volatile("red.global.add.v4.f32 [%0], {%1, %2, %3, %4};"
                 :: "l"(p), "f"(a), "f"(b), "f"(c), "f"(d)
                 : "memory");
}

// ---------------------------------------------------------------------------
// kernel 0: build E0 = concat(user, item); seed front=E0; write out[:, 0:64]
// ---------------------------------------------------------------------------
__global__ void k_init(const float* __restrict__ user, const float* __restrict__ item,
                       float* __restrict__ out) {
    int idx = blockIdx.x * blockDim.x + threadIdx.x;  // one float4 per thread
    if (idx >= N_NODES * (D / 4)) return;
    int row = idx >> 4;
    int c4 = (idx & 15) << 2;
    float4 v;
    if (row < N_USER)
        v = *reinterpret_cast<const float4*>(&user[row * D + c4]);
    else
        v = *reinterpret_cast<const float4*>(&item[(row - N_USER) * D + c4]);
    *reinterpret_cast<float4*>(&g_E[row * D + c4]) = v;
    *reinterpret_cast<float4*>(&g_front[row * D + c4]) = v;   // +I seed for spmm
    *reinterpret_cast<float4*>(&out[row * OUTD + c4]) = v;
}

// ---------------------------------------------------------------------------
// kernel 1: SpMM scatter: front[row] += val * E[col], 16 threads per edge
// ---------------------------------------------------------------------------
__global__ void k_spmm(const int* __restrict__ erow, const int* __restrict__ ecol,
                       const float* __restrict__ eval_) {
    int tid = blockIdx.x * blockDim.x + threadIdx.x;
    int e = tid >> 4;
    if (e >= N_EDGES) return;
    int c4 = (tid & 15) << 2;
    int r = __ldg(&erow[e]);
    int c = __ldg(&ecol[e]);
    float v = __ldg(&eval_[e]);
    float4 x = *reinterpret_cast<const float4*>(&g_E[c * D + c4]);
    red_add_v4(&g_front[r * D + c4], v * x.x, v * x.y, v * x.z, v * x.w);
}

// ---------------------------------------------------------------------------
// kernel 2: dense layer.
//   o = lrelu(front @ Wf^T + bf) + lrelu((E*front) @ Wb^T + bb)
//   E <- o ; front <- o (pre-seed next layer's +I) ; out[:, 64*(l+1):...] = o/||o||
// blockDim (32,4). Each warp processes 8 rows as 4 f32x2-packed row pairs.
// Per-k LDS: 1x LDS.128 (packed W quad) + 4x LDS.128 broadcast (xy) = 5 issues.
// ---------------------------------------------------------------------------
#define GROUPS (N_NODES / 8)          // 18750
#define DENSE_BLOCKS ((GROUPS + 3) / 4)

__global__ __launch_bounds__(128) void k_dense(const float* __restrict__ Wf,
                                               const float* __restrict__ bf,
                                               const float* __restrict__ Wb,
                                               const float* __restrict__ bb,
                                               float* __restrict__ out, int layer) {
    // Wc[k][j] = { Wf[j][k], Wf[j+32][k], Wb[j][k], Wb[j+32][k] }   (32 KB)
    __shared__ float4 Wc[D][32];
    // xy[warp][pair][k] = { front_r0[k], front_r1[k], (E*front)_r0[k], (E*front)_r1[k] } (16 KB)
    __shared__ float4 xy[4][4][D];

    int tid = threadIdx.y * 32 + threadIdx.x;
    int lane = threadIdx.x;
    int ty = threadIdx.y;

    // build packed W (16 KB global reads per block, L2-resident)
    for (int t = tid; t < D * 32; t += 128) {
        int k = t >> 5, j = t & 31;
        Wc[k][j] = make_float4(Wf[j * D + k], Wf[(j + 32) * D + k],
                               Wb[j * D + k], Wb[(j + 32) * D + k]);
    }
    __syncthreads();

    int group = blockIdx.x * 4 + ty;
    if (group >= GROUPS) return;
    int rb = group * 8;

    // stage 8 rows (4 pairs): float2 loads, interleaved float4 stores
    int k2 = lane * 2;
    #pragma unroll
    for (int p = 0; p < 4; p++) {
        int r0 = (rb + 2 * p) * D;
        int r1 = r0 + D;
        float2 x0 = *reinterpret_cast<const float2*>(&g_front[r0 + k2]);
        float2 x1 = *reinterpret_cast<const float2*>(&g_front[r1 + k2]);
        float2 e0 = *reinterpret_cast<const float2*>(&g_E[r0 + k2]);
        float2 e1 = *reinterpret_cast<const float2*>(&g_E[r1 + k2]);
        xy[ty][p][k2]     = make_float4(x0.x, x1.x, x0.x * e0.x, x1.x * e1.x);
        xy[ty][p][k2 + 1] = make_float4(x0.y, x1.y, x0.y * e0.y, x1.y * e1.y);
    }
    __syncwarp();

    float bfv0 = bf[lane], bfv1 = bf[lane + 32];
    float bbv0 = bb[lane], bbv1 = bb[lane + 32];

    unsigned long long sf0[4], sf1[4], sb0[4], sb1[4];
    #pragma unroll
    for (int p = 0; p < 4; p++) {
        sf0[p] = pk2(bfv0, bfv0);
        sf1[p] = pk2(bfv1, bfv1);
        sb0[p] = pk2(bbv0, bbv0);
        sb1[p] = pk2(bbv1, bbv1);
    }

    #pragma unroll 4
    for (int k = 0; k < D; k++) {
        float4 w = Wc[k][lane];
        unsigned long long wf0p = pk2(w.x, w.x);
        unsigned long long wf1p = pk2(w.y, w.y);
        unsigned long long wb0p = pk2(w.z, w.z);
        unsigned long long wb1p = pk2(w.w, w.w);
        #pragma unroll
        for (int p = 0; p < 4; p++) {
            ulonglong2 v = *reinterpret_cast<const ulonglong2*>(&xy[ty][p][k]);
            fma2(sf0[p], v.x, wf0p);
            fma2(sf1[p], v.x, wf1p);
            fma2(sb0[p], v.y, wb0p);
            fma2(sb1[p], v.y, wb1p);
        }
    }

    int ocol = (layer + 1) * D;
    #pragma unroll
    for (int p = 0; p < 4; p++) {
        float f0lo, f0hi, f1lo, f1hi, b0lo, b0hi, b1lo, b1hi;
        unpk2(f0lo, f0hi, sf0[p]);
        unpk2(f1lo, f1hi, sf1[p]);
        unpk2(b0lo, b0hi, sb0[p]);
        unpk2(b1lo, b1hi, sb1[p]);

        int row0 = rb + 2 * p;
        int row1 = row0 + 1;

        float o00 = lrelu(f0lo) + lrelu(b0lo);  // row0, j=lane
        float o01 = lrelu(f1lo) + lrelu(b1lo);  // row0, j=lane+32
        float o10 = lrelu(f0hi) + lrelu(b0hi);  // row1, j=lane
        float o11 = lrelu(f1hi) + lrelu(b1hi);  // row1, j=lane+32

        float ss0 = o00 * o00 + o01 * o01;
        float ss1 = o10 * o10 + o11 * o11;
        #pragma unroll
        for (int d = 16; d > 0; d >>= 1) {
            ss0 += __shfl_xor_sync(0xffffffffu, ss0, d);
            ss1 += __shfl_xor_sync(0xffffffffu, ss1, d);
        }
        float inv0 = 1.f / fmaxf(sqrtf(ss0), EPS_NORM);
        float inv1 = 1.f / fmaxf(sqrtf(ss1), EPS_NORM);

        g_E[row0 * D + lane] = o00;
        g_E[row0 * D + 32 + lane] = o01;
        g_E[row1 * D + lane] = o10;
        g_E[row1 * D + 32 + lane] = o11;

        // pre-seed next layer's front = E (+I term), replaces k_copy
        g_front[row0 * D + lane] = o00;
        g_front[row0 * D + 32 + lane] = o01;
        g_front[row1 * D + lane] = o10;
        g_front[row1 * D + 32 + lane] = o11;

        out[row0 * OUTD + ocol + lane] = o00 * inv0;
        out[row0 * OUTD + ocol + 32 + lane] = o01 * inv0;
        out[row1 * OUTD + ocol + lane] = o10 * inv1;
        out[row1 * OUTD + ocol + 32 + lane] = o11 * inv1;
    }
}

// ---------------------------------------------------------------------------
extern "C" void kernel_launch(void* const* d_in, const int* in_sizes, int n_in,
                              void* d_out, int out_size) {
    const float* user = (const float*)d_in[0];
    const float* item = (const float*)d_in[1];
    const int* erow = (const int*)d_in[2];
    const int* ecol = (const int*)d_in[3];
    const float* eval_ = (const float*)d_in[4];
    const float* Wf = (const float*)d_in[5];
    const float* bf = (const float*)d_in[6];
    const float* Wb = (const float*)d_in[7];
    const float* bb = (const float*)d_in[8];
    float* out = (float*)d_out;

    const int vec_elems = N_NODES * (D / 4);               // 2.4M float4 units
    const int vec_blocks = (vec_elems + 255) / 256;
    const int spmm_blocks = (N_EDGES * 16 + 255) / 256;    // 75000

    k_init<<<vec_blocks, 256>>>(user, item, out);
    for (int l = 0; l < 3; l++) {
        k_spmm<<<spmm_blocks, 256>>>(erow, ecol, eval_);
        k_dense<<<DENSE_BLOCKS, dim3(32, 4)>>>(Wf + l * D * D, bf + l * D,
                                               Wb + l * D * D, bb + l * D, out, l);
    }
}

// round 3
// speedup vs baseline: 2.7912x; 2.7912x over previous
#include <cuda_runtime.h>
#include <cuda_bf16.h>
#include <cstdint>

#define N_USER 100000
#define N_ITEM 50000
#define N_NODES 150000
#define N_EDGES 1200000
#define D 64
#define OUTD 256
#define NEG_SLOPE 0.01f
#define EPS_NORM 1e-12f

// Scratch (device globals allowed; no dynamic allocation)
__device__ float g_E[N_NODES * D];      // current layer embedding (unnormalized)
__device__ float g_front[N_NODES * D];  // (H+I) @ E accumulator
__device__ float4 g_Wpack[3 * 2048];    // packed W quads per layer:
// g_Wpack[l*2048 + k*32 + j] = { Wf[j][k], Wf[j+32][k], Wb[j][k], Wb[j+32][k] }

// ---------------------------------------------------------------------------
// helpers
// ---------------------------------------------------------------------------
__device__ __forceinline__ float lrelu(float v) {
    return v >= 0.f ? v : NEG_SLOPE * v;
}

__device__ __forceinline__ unsigned long long pk2(float lo, float hi) {
    unsigned long long r;
    asm("mov.b64 %0, {%1, %2};" : "=l"(r) : "f"(lo), "f"(hi));
    return r;
}
__device__ __forceinline__ void unpk2(float& lo, float& hi, unsigned long long v) {
    asm("mov.b64 {%0, %1}, %2;" : "=f"(lo), "=f"(hi) : "l"(v));
}
__device__ __forceinline__ void fma2(unsigned long long& d, unsigned long long a,
                                     unsigned long long b) {
    asm("fma.rn.f32x2 %0, %1, %2, %0;" : "+l"(d) : "l"(a), "l"(b));
}

__device__ __forceinline__ void red_add_v4(float* p, float a, float b, float c, float d) {
    asm volatile("red.global.add.v4.f32 [%0], {%1, %2, %3, %4};"
                 :: "l"(p), "f"(a), "f"(b), "f"(c), "f"(d)
                 : "memory");
}

// ---------------------------------------------------------------------------
// kernel P: pack W for all 3 layers (one-time gather; tiny)
// ---------------------------------------------------------------------------
__global__ void k_prep(const float* __restrict__ Wf, const float* __restrict__ Wb) {
    int u = blockIdx.x * blockDim.x + threadIdx.x;
    if (u >= 3 * 2048) return;
    int l = u >> 11;
    int t = u & 2047;
    int k = t >> 5;
    int j = t & 31;
    const float* wf = Wf + l * D * D;
    const float* wb = Wb + l * D * D;
    g_Wpack[u] = make_float4(wf[j * D + k], wf[(j + 32) * D + k],
                             wb[j * D + k], wb[(j + 32) * D + k]);
}

// ---------------------------------------------------------------------------
// kernel 0: build E0 = concat(user, item); seed front=E0; write out[:, 0:64]
// ---------------------------------------------------------------------------
__global__ void k_init(const float* __restrict__ user, const float* __restrict__ item,
                       float* __restrict__ out) {
    int idx = blockIdx.x * blockDim.x + threadIdx.x;  // one float4 per thread
    if (idx >= N_NODES * (D / 4)) return;
    int row = idx >> 4;
    int c4 = (idx & 15) << 2;
    float4 v;
    if (row < N_USER)
        v = *reinterpret_cast<const float4*>(&user[row * D + c4]);
    else
        v = *reinterpret_cast<const float4*>(&item[(row - N_USER) * D + c4]);
    *reinterpret_cast<float4*>(&g_E[row * D + c4]) = v;
    *reinterpret_cast<float4*>(&g_front[row * D + c4]) = v;   // +I seed for spmm
    *reinterpret_cast<float4*>(&out[row * OUTD + c4]) = v;
}

// ---------------------------------------------------------------------------
// kernel 1: SpMM scatter: front[row] += val * E[col], 16 threads per edge
// ---------------------------------------------------------------------------
__global__ void k_spmm(const int* __restrict__ erow, const int* __restrict__ ecol,
                       const float* __restrict__ eval_) {
    int tid = blockIdx.x * blockDim.x + threadIdx.x;
    int e = tid >> 4;
    if (e >= N_EDGES) return;
    int c4 = (tid & 15) << 2;
    int r = __ldg(&erow[e]);
    int c = __ldg(&ecol[e]);
    float v = __ldg(&eval_[e]);
    float4 x = *reinterpret_cast<const float4*>(&g_E[c * D + c4]);
    red_add_v4(&g_front[r * D + c4], v * x.x, v * x.y, v * x.z, v * x.w);
}

// ---------------------------------------------------------------------------
// kernel 2: dense layer.
//   o = lrelu(front @ Wf^T + bf) + lrelu((E*front) @ Wb^T + bb)
//   E <- o ; front <- o (pre-seed next layer's +I) ; out[:, 64*(l+1):...] = o/||o||
// blockDim (32,8). Each warp processes 8 rows as 4 f32x2-packed row pairs.
// Per-k per-warp LDS: 1x LDS.128 (W quad) + 4x LDS.128 broadcast (xy) = 5 issues.
// ---------------------------------------------------------------------------
#define GROUPS (N_NODES / 8)          // 18750
#define DENSE_WARPS 8
#define DENSE_BLOCKS ((GROUPS + DENSE_WARPS - 1) / DENSE_WARPS)

__global__ __launch_bounds__(32 * DENSE_WARPS) void k_dense(
        const float* __restrict__ bf, const float* __restrict__ bb,
        float* __restrict__ out, int layer) {
    __shared__ float4 Wc[D * 32];                    // 32 KB, packed quads
    __shared__ float4 xy[DENSE_WARPS][4][D];         // 32 KB

    int tid = threadIdx.y * 32 + threadIdx.x;
    int lane = threadIdx.x;
    int ty = threadIdx.y;

    // coalesced copy of pre-packed W (conflict-free linear STS.128)
    const float4* wsrc = g_Wpack + layer * 2048;
    #pragma unroll
    for (int t = tid; t < 2048; t += 32 * DENSE_WARPS) Wc[t] = wsrc[t];
    __syncthreads();

    int group = blockIdx.x * DENSE_WARPS + ty;
    if (group >= GROUPS) return;
    int rb = group * 8;

    // stage 8 rows (4 pairs): float2 loads, interleaved float4 stores
    int k2 = lane * 2;
    #pragma unroll
    for (int p = 0; p < 4; p++) {
        int r0 = (rb + 2 * p) * D;
        int r1 = r0 + D;
        float2 x0 = *reinterpret_cast<const float2*>(&g_front[r0 + k2]);
        float2 x1 = *reinterpret_cast<const float2*>(&g_front[r1 + k2]);
        float2 e0 = *reinterpret_cast<const float2*>(&g_E[r0 + k2]);
        float2 e1 = *reinterpret_cast<const float2*>(&g_E[r1 + k2]);
        xy[ty][p][k2]     = make_float4(x0.x, x1.x, x0.x * e0.x, x1.x * e1.x);
        xy[ty][p][k2 + 1] = make_float4(x0.y, x1.y, x0.y * e0.y, x1.y * e1.y);
    }
    __syncwarp();

    float bfv0 = bf[lane], bfv1 = bf[lane + 32];
    float bbv0 = bb[lane], bbv1 = bb[lane + 32];

    unsigned long long sf0[4], sf1[4], sb0[4], sb1[4];
    #pragma unroll
    for (int p = 0; p < 4; p++) {
        sf0[p] = pk2(bfv0, bfv0);
        sf1[p] = pk2(bfv1, bfv1);
        sb0[p] = pk2(bbv0, bbv0);
        sb1[p] = pk2(bbv1, bbv1);
    }

    #pragma unroll 4
    for (int k = 0; k < D; k++) {
        float4 w = Wc[k * 32 + lane];
        unsigned long long wf0p = pk2(w.x, w.x);
        unsigned long long wf1p = pk2(w.y, w.y);
        unsigned long long wb0p = pk2(w.z, w.z);
        unsigned long long wb1p = pk2(w.w, w.w);
        #pragma unroll
        for (int p = 0; p < 4; p++) {
            ulonglong2 v = *reinterpret_cast<const ulonglong2*>(&xy[ty][p][k]);
            fma2(sf0[p], v.x, wf0p);
            fma2(sf1[p], v.x, wf1p);
            fma2(sb0[p], v.y, wb0p);
            fma2(sb1[p], v.y, wb1p);
        }
    }

    int ocol = (layer + 1) * D;
    #pragma unroll
    for (int p = 0; p < 4; p++) {
        float f0lo, f0hi, f1lo, f1hi, b0lo, b0hi, b1lo, b1hi;
        unpk2(f0lo, f0hi, sf0[p]);
        unpk2(f1lo, f1hi, sf1[p]);
        unpk2(b0lo, b0hi, sb0[p]);
        unpk2(b1lo, b1hi, sb1[p]);

        int row0 = rb + 2 * p;
        int row1 = row0 + 1;

        float o00 = lrelu(f0lo) + lrelu(b0lo);  // row0, j=lane
        float o01 = lrelu(f1lo) + lrelu(b1lo);  // row0, j=lane+32
        float o10 = lrelu(f0hi) + lrelu(b0hi);  // row1, j=lane
        float o11 = lrelu(f1hi) + lrelu(b1hi);  // row1, j=lane+32

        float ss0 = o00 * o00 + o01 * o01;
        float ss1 = o10 * o10 + o11 * o11;
        #pragma unroll
        for (int d = 16; d > 0; d >>= 1) {
            ss0 += __shfl_xor_sync(0xffffffffu, ss0, d);
            ss1 += __shfl_xor_sync(0xffffffffu, ss1, d);
        }
        float inv0 = 1.f / fmaxf(sqrtf(ss0), EPS_NORM);
        float inv1 = 1.f / fmaxf(sqrtf(ss1), EPS_NORM);

        g_E[row0 * D + lane] = o00;
        g_E[row0 * D + 32 + lane] = o01;
        g_E[row1 * D + lane] = o10;
        g_E[row1 * D + 32 + lane] = o11;

        // pre-seed next layer's front = E (+I term)
        g_front[row0 * D + lane] = o00;
        g_front[row0 * D + 32 + lane] = o01;
        g_front[row1 * D + lane] = o10;
        g_front[row1 * D + 32 + lane] = o11;

        out[row0 * OUTD + ocol + lane] = o00 * inv0;
        out[row0 * OUTD + ocol + 32 + lane] = o01 * inv0;
        out[row1 * OUTD + ocol + lane] = o10 * inv1;
        out[row1 * OUTD + ocol + 32 + lane] = o11 * inv1;
    }
}

// ---------------------------------------------------------------------------
extern "C" void kernel_launch(void* const* d_in, const int* in_sizes, int n_in,
                              void* d_out, int out_size) {
    const float* user = (const float*)d_in[0];
    const float* item = (const float*)d_in[1];
    const int* erow = (const int*)d_in[2];
    const int* ecol = (const int*)d_in[3];
    const float* eval_ = (const float*)d_in[4];
    const float* Wf = (const float*)d_in[5];
    const float* bf = (const float*)d_in[6];
    const float* Wb = (const float*)d_in[7];
    const float* bb = (const float*)d_in[8];
    float* out = (float*)d_out;

    const int vec_elems = N_NODES * (D / 4);               // 2.4M float4 units
    const int vec_blocks = (vec_elems + 255) / 256;
    const int spmm_blocks = (N_EDGES * 16 + 255) / 256;    // 75000

    k_prep<<<24, 256>>>(Wf, Wb);
    k_init<<<vec_blocks, 256>>>(user, item, out);
    for (int l = 0; l < 3; l++) {
        k_spmm<<<spmm_blocks, 256>>>(erow, ecol, eval_);
        k_dense<<<DENSE_BLOCKS, dim3(32, DENSE_WARPS)>>>(bf + l * D, bb + l * D, out, l);
    }
}

// round 4
// speedup vs baseline: 3.0729x; 1.1009x over previous
#include <cuda_runtime.h>
#include <cuda_bf16.h>
#include <cstdint>

#define N_USER 100000
#define N_ITEM 50000
#define N_NODES 150000
#define N_EDGES 1200000
#define D 64
#define OUTD 256
#define NEG_SLOPE 0.01f
#define EPS_NORM 1e-12f

#define SCAN_BLK 1024
#define SCAN_NBLK ((N_NODES + SCAN_BLK - 1) / SCAN_BLK)   // 147

// Scratch (device globals; no dynamic allocation)
__device__ float g_E[N_NODES * D];        // current layer embedding (unnormalized)
__device__ float g_front[N_NODES * D];    // (H+I) @ E result
__device__ float4 g_Wpack[3 * 2048];      // packed W quads per layer
__device__ int g_cnt[N_NODES];            // degree histogram
__device__ int g_off[N_NODES + 1];        // CSR row offsets
__device__ int g_cur[N_NODES];            // scatter cursors
__device__ float2 g_edge[N_EDGES];        // {bitcast(col), val} per slot
__device__ int g_blksum[SCAN_NBLK];

// ---------------------------------------------------------------------------
// helpers
// ---------------------------------------------------------------------------
__device__ __forceinline__ float lrelu(float v) {
    return v >= 0.f ? v : NEG_SLOPE * v;
}
__device__ __forceinline__ unsigned long long pk2(float lo, float hi) {
    unsigned long long r;
    asm("mov.b64 %0, {%1, %2};" : "=l"(r) : "f"(lo), "f"(hi));
    return r;
}
__device__ __forceinline__ void unpk2(float& lo, float& hi, unsigned long long v) {
    asm("mov.b64 {%0, %1}, %2;" : "=f"(lo), "=f"(hi) : "l"(v));
}
__device__ __forceinline__ void fma2(unsigned long long& d, unsigned long long a,
                                     unsigned long long b) {
    asm("fma.rn.f32x2 %0, %1, %2, %0;" : "+l"(d) : "l"(a), "l"(b));
}

// ---------------------------------------------------------------------------
// CSR build: zero -> hist -> scan(3) -> scatter
// ---------------------------------------------------------------------------
__global__ void k_zero() {
    int i = blockIdx.x * blockDim.x + threadIdx.x;
    if (i < N_NODES) g_cnt[i] = 0;
}

__global__ void k_hist(const int* __restrict__ erow) {
    int e = blockIdx.x * blockDim.x + threadIdx.x;
    if (e >= N_EDGES) return;
    atomicAdd(&g_cnt[__ldg(&erow[e])], 1);
}

__global__ void k_scan1() {
    __shared__ int s[SCAN_BLK];
    int i = blockIdx.x * SCAN_BLK + threadIdx.x;
    int v = (i < N_NODES) ? g_cnt[i] : 0;
    s[threadIdx.x] = v;
    __syncthreads();
    #pragma unroll
    for (int d = 1; d < SCAN_BLK; d <<= 1) {
        int t = (threadIdx.x >= d) ? s[threadIdx.x - d] : 0;
        __syncthreads();
        s[threadIdx.x] += t;
        __syncthreads();
    }
    if (i < N_NODES) g_off[i] = s[threadIdx.x] - v;     // exclusive within block
    if (threadIdx.x == SCAN_BLK - 1) g_blksum[blockIdx.x] = s[SCAN_BLK - 1];
}

__global__ void k_scan2() {   // one block of 256 >= SCAN_NBLK
    __shared__ int s[256];
    int v = (threadIdx.x < SCAN_NBLK) ? g_blksum[threadIdx.x] : 0;
    s[threadIdx.x] = v;
    __syncthreads();
    #pragma unroll
    for (int d = 1; d < 256; d <<= 1) {
        int t = (threadIdx.x >= d) ? s[threadIdx.x - d] : 0;
        __syncthreads();
        s[threadIdx.x] += t;
        __syncthreads();
    }
    if (threadIdx.x < SCAN_NBLK) g_blksum[threadIdx.x] = s[threadIdx.x] - v;
}

__global__ void k_scan3() {
    int i = blockIdx.x * SCAN_BLK + threadIdx.x;
    if (i >= N_NODES) return;
    int o = g_off[i] + g_blksum[i >> 10];
    g_off[i] = o;
    g_cur[i] = o;
    if (i == 0) g_off[N_NODES] = N_EDGES;
}

__global__ void k_scatter(const int* __restrict__ erow, const int* __restrict__ ecol,
                          const float* __restrict__ eval_) {
    int e = blockIdx.x * blockDim.x + threadIdx.x;
    if (e >= N_EDGES) return;
    int r = __ldg(&erow[e]);
    int pos = atomicAdd(&g_cur[r], 1);
    g_edge[pos] = make_float2(__int_as_float(__ldg(&ecol[e])), __ldg(&eval_[e]));
}

// ---------------------------------------------------------------------------
// kernel P: pack W for all 3 layers (one-time gather; tiny)
// g_Wpack[l*2048 + k*32 + j] = { Wf[j][k], Wf[j+32][k], Wb[j][k], Wb[j+32][k] }
// ---------------------------------------------------------------------------
__global__ void k_prep(const float* __restrict__ Wf, const float* __restrict__ Wb) {
    int u = blockIdx.x * blockDim.x + threadIdx.x;
    if (u >= 3 * 2048) return;
    int l = u >> 11;
    int t = u & 2047;
    int k = t >> 5;
    int j = t & 31;
    const float* wf = Wf + l * D * D;
    const float* wb = Wb + l * D * D;
    g_Wpack[u] = make_float4(wf[j * D + k], wf[(j + 32) * D + k],
                             wb[j * D + k], wb[(j + 32) * D + k]);
}

// ---------------------------------------------------------------------------
// kernel 0: build E0 = concat(user, item); write out[:, 0:64]
// ---------------------------------------------------------------------------
__global__ void k_init(const float* __restrict__ user, const float* __restrict__ item,
                       float* __restrict__ out) {
    int idx = blockIdx.x * blockDim.x + threadIdx.x;  // one float4 per thread
    if (idx >= N_NODES * (D / 4)) return;
    int row = idx >> 4;
    int c4 = (idx & 15) << 2;
    float4 v;
    if (row < N_USER)
        v = *reinterpret_cast<const float4*>(&user[row * D + c4]);
    else
        v = *reinterpret_cast<const float4*>(&item[(row - N_USER) * D + c4]);
    *reinterpret_cast<float4*>(&g_E[row * D + c4]) = v;
    *reinterpret_cast<float4*>(&out[row * OUTD + c4]) = v;
}

// ---------------------------------------------------------------------------
// kernel 1: gather SpMM: front[row] = E[row] + sum_e val_e * E[col_e]
// warp per row, lane holds features {2*lane, 2*lane+1}, 2-edge unroll for MLP
// ---------------------------------------------------------------------------
__global__ __launch_bounds__(256) void k_spmm() {
    int row = blockIdx.x * 8 + threadIdx.y;
    if (row >= N_NODES) return;
    int lane = threadIdx.x;
    const float2* E2 = reinterpret_cast<const float2*>(g_E);
    float2* F2 = reinterpret_cast<float2*>(g_front);

    int i = __ldg(&g_off[row]);
    int end = __ldg(&g_off[row + 1]);

    float2 acc = E2[row * 32 + lane];                 // +I term
    float2 acc2 = make_float2(0.f, 0.f);

    for (; i + 1 < end; i += 2) {
        float2 p0 = g_edge[i];
        float2 p1 = g_edge[i + 1];
        int c0 = __float_as_int(p0.x);
        int c1 = __float_as_int(p1.x);
        float2 x0 = E2[c0 * 32 + lane];
        float2 x1 = E2[c1 * 32 + lane];
        acc.x = fmaf(p0.y, x0.x, acc.x);
        acc.y = fmaf(p0.y, x0.y, acc.y);
        acc2.x = fmaf(p1.y, x1.x, acc2.x);
        acc2.y = fmaf(p1.y, x1.y, acc2.y);
    }
    if (i < end) {
        float2 p0 = g_edge[i];
        int c0 = __float_as_int(p0.x);
        float2 x0 = E2[c0 * 32 + lane];
        acc.x = fmaf(p0.y, x0.x, acc.x);
        acc.y = fmaf(p0.y, x0.y, acc.y);
    }
    acc.x += acc2.x;
    acc.y += acc2.y;
    F2[row * 32 + lane] = acc;
}

// ---------------------------------------------------------------------------
// kernel 2: dense layer.
//   o = lrelu(front @ Wf^T + bf) + lrelu((E*front) @ Wb^T + bb)
//   E <- o (skipped on last layer) ; out[:, 64*(l+1):...] = o/||o||
// ---------------------------------------------------------------------------
#define GROUPS (N_NODES / 8)          // 18750
#define DENSE_WARPS 8
#define DENSE_BLOCKS ((GROUPS + DENSE_WARPS - 1) / DENSE_WARPS)

__global__ __launch_bounds__(32 * DENSE_WARPS) void k_dense(
        const float* __restrict__ bf, const float* __restrict__ bb,
        float* __restrict__ out, int layer) {
    __shared__ float4 Wc[D * 32];                    // 32 KB, packed quads
    __shared__ float4 xy[DENSE_WARPS][4][D];         // 32 KB

    int tid = threadIdx.y * 32 + threadIdx.x;
    int lane = threadIdx.x;
    int ty = threadIdx.y;

    const float4* wsrc = g_Wpack + layer * 2048;
    #pragma unroll
    for (int t = tid; t < 2048; t += 32 * DENSE_WARPS) Wc[t] = wsrc[t];
    __syncthreads();

    int group = blockIdx.x * DENSE_WARPS + ty;
    if (group >= GROUPS) return;
    int rb = group * 8;

    int k2 = lane * 2;
    #pragma unroll
    for (int p = 0; p < 4; p++) {
        int r0 = (rb + 2 * p) * D;
        int r1 = r0 + D;
        float2 x0 = *reinterpret_cast<const float2*>(&g_front[r0 + k2]);
        float2 x1 = *reinterpret_cast<const float2*>(&g_front[r1 + k2]);
        float2 e0 = *reinterpret_cast<const float2*>(&g_E[r0 + k2]);
        float2 e1 = *reinterpret_cast<const float2*>(&g_E[r1 + k2]);
        xy[ty][p][k2]     = make_float4(x0.x, x1.x, x0.x * e0.x, x1.x * e1.x);
        xy[ty][p][k2 + 1] = make_float4(x0.y, x1.y, x0.y * e0.y, x1.y * e1.y);
    }
    __syncwarp();

    float bfv0 = bf[lane], bfv1 = bf[lane + 32];
    float bbv0 = bb[lane], bbv1 = bb[lane + 32];

    unsigned long long sf0[4], sf1[4], sb0[4], sb1[4];
    #pragma unroll
    for (int p = 0; p < 4; p++) {
        sf0[p] = pk2(bfv0, bfv0);
        sf1[p] = pk2(bfv1, bfv1);
        sb0[p] = pk2(bbv0, bbv0);
        sb1[p] = pk2(bbv1, bbv1);
    }

    #pragma unroll 4
    for (int k = 0; k < D; k++) {
        float4 w = Wc[k * 32 + lane];
        unsigned long long wf0p = pk2(w.x, w.x);
        unsigned long long wf1p = pk2(w.y, w.y);
        unsigned long long wb0p = pk2(w.z, w.z);
        unsigned long long wb1p = pk2(w.w, w.w);
        #pragma unroll
        for (int p = 0; p < 4; p++) {
            ulonglong2 v = *reinterpret_cast<const ulonglong2*>(&xy[ty][p][k]);
            fma2(sf0[p], v.x, wf0p);
            fma2(sf1[p], v.x, wf1p);
            fma2(sb0[p], v.y, wb0p);
            fma2(sb1[p], v.y, wb1p);
        }
    }

    int ocol = (layer + 1) * D;
    bool keep = (layer != 2);
    #pragma unroll
    for (int p = 0; p < 4; p++) {
        float f0lo, f0hi, f1lo, f1hi, b0lo, b0hi, b1lo, b1hi;
        unpk2(f0lo, f0hi, sf0[p]);
        unpk2(f1lo, f1hi, sf1[p]);
        unpk2(b0lo, b0hi, sb0[p]);
        unpk2(b1lo, b1hi, sb1[p]);

        int row0 = rb + 2 * p;
        int row1 = row0 + 1;

        float o00 = lrelu(f0lo) + lrelu(b0lo);
        float o01 = lrelu(f1lo) + lrelu(b1lo);
        float o10 = lrelu(f0hi) + lrelu(b0hi);
        float o11 = lrelu(f1hi) + lrelu(b1hi);

        float ss0 = o00 * o00 + o01 * o01;
        float ss1 = o10 * o10 + o11 * o11;
        #pragma unroll
        for (int d = 16; d > 0; d >>= 1) {
            ss0 += __shfl_xor_sync(0xffffffffu, ss0, d);
            ss1 += __shfl_xor_sync(0xffffffffu, ss1, d);
        }
        float inv0 = 1.f / fmaxf(sqrtf(ss0), EPS_NORM);
        float inv1 = 1.f / fmaxf(sqrtf(ss1), EPS_NORM);

        if (keep) {
            g_E[row0 * D + lane] = o00;
            g_E[row0 * D + 32 + lane] = o01;
            g_E[row1 * D + lane] = o10;
            g_E[row1 * D + 32 + lane] = o11;
        }

        out[row0 * OUTD + ocol + lane] = o00 * inv0;
        out[row0 * OUTD + ocol + 32 + lane] = o01 * inv0;
        out[row1 * OUTD + ocol + lane] = o10 * inv1;
        out[row1 * OUTD + ocol + 32 + lane] = o11 * inv1;
    }
}

// ---------------------------------------------------------------------------
extern "C" void kernel_launch(void* const* d_in, const int* in_sizes, int n_in,
                              void* d_out, int out_size) {
    const float* user = (const float*)d_in[0];
    const float* item = (const float*)d_in[1];
    const int* erow = (const int*)d_in[2];
    const int* ecol = (const int*)d_in[3];
    const float* eval_ = (const float*)d_in[4];
    const float* Wf = (const float*)d_in[5];
    const float* bf = (const float*)d_in[6];
    const float* Wb = (const float*)d_in[7];
    const float* bb = (const float*)d_in[8];
    float* out = (float*)d_out;

    const int vec_elems = N_NODES * (D / 4);
    const int vec_blocks = (vec_elems + 255) / 256;
    const int edge_blocks = (N_EDGES + 255) / 256;
    const int node_blocks = (N_NODES + 255) / 256;
    const int spmm_blocks = (N_NODES + 7) / 8;

    // CSR build (one-time per replay)
    k_zero<<<node_blocks, 256>>>();
    k_hist<<<edge_blocks, 256>>>(erow);
    k_scan1<<<SCAN_NBLK, SCAN_BLK>>>();
    k_scan2<<<1, 256>>>();
    k_scan3<<<SCAN_NBLK, SCAN_BLK>>>();
    k_scatter<<<edge_blocks, 256>>>(erow, ecol, eval_);

    k_prep<<<24, 256>>>(Wf, Wb);
    k_init<<<vec_blocks, 256>>>(user, item, out);
    for (int l = 0; l < 3; l++) {
        k_spmm<<<spmm_blocks, dim3(32, 8)>>>();
        k_dense<<<DENSE_BLOCKS, dim3(32, DENSE_WARPS)>>>(bf + l * D, bb + l * D, out, l);
    }
}